// round 5
// baseline (speedup 1.0000x reference)
#include <cuda_runtime.h>

// LearnableShiftViews: out[v,b,c,h,w] = separable bilinear resample of x[b,c]
// at pix = (idx + d)*size/(size-1) - 0.5 per axis, zero padding.
//
// R5: kernel is L1tex-wavefront bound (85%). Halve the data-LDS count by
// row-register reuse: thread is fixed at x and walks the 8 output rows of a
// view; consecutive rows share an input row (r0(ty+1)==r1(ty) except at rare
// sy>1 double-steps / clamp edges), so keep the bottom row's two taps in
// registers and reload only the new row (2 LDS.32/output steady state).
// The reuse test is on warp-uniform row byte-offsets -> uniform predication;
// predicated-off LDS creates no wavefront. Zero-padded smem rows keep the
// x-blend mask-free. Held registers reset per view (dx changes the column).

namespace {

constexpr int H = 224;
constexpr int W = 224;
constexpr int B = 64;
constexpr int C = 3;
constexpr int BCN = B * C;   // 192
constexpr int V = 5;
constexpr int TILE_Y = 8;
constexpr int ROWS_CAP = 16;
constexpr int NTHREADS = 224;          // 7 warps; tid == output x
constexpr int RS = 228;                // [0,1]=pad0, [2..225]=data, [226,227]=pad0

__global__ __launch_bounds__(NTHREADS, 6)
void shift_views_kernel(const float* __restrict__ x,
                        const float* __restrict__ offs,
                        float* __restrict__ out) {
    __shared__ float  srows[ROWS_CAP * RS];
    __shared__ float4 ycoef[V][TILE_Y];   // {wy0, wy1, byteoff(row0), byteoff(row1)}

    const int yb  = blockIdx.x * TILE_Y;
    const int bc  = blockIdx.y;
    const int tid = threadIdx.x;
    const float sy = (float)H / (float)(H - 1);
    const float sx = (float)W / (float)(W - 1);

    // ---- Row range needed across all views (endpoints suffice; monotone).
    int rmin = H - 1, rmax = 0;
#pragma unroll
    for (int v = 0; v < V; ++v) {
        float dy = __ldg(&offs[2 * v]);
        int lo = (int)floorf(((float)yb + dy) * sy - 0.5f);
        int hi = (int)floorf(((float)(yb + TILE_Y - 1) + dy) * sy - 0.5f) + 1;
        lo = max(lo, 0);
        hi = min(hi, H - 1);
        rmin = min(rmin, lo);
        rmax = max(rmax, hi);
    }
    if (rmin > rmax) { rmin = 0; rmax = 0; }
    rmax = min(rmax, rmin + ROWS_CAP - 1);
    const int nrows = rmax - rmin + 1;

    // ---- Zero the 4 pad columns of every staged row.
    if (tid < ROWS_CAP * 4) {
        int r = tid >> 2, c = tid & 3;
        srows[r * RS + (c < 2 ? c : 224 + c)] = 0.0f;   // cols 0,1,226,227
    }

    // ---- Build y-coefficient table: one thread per (v, ty).
    if (tid < V * TILE_Y) {
        int v  = tid >> 3;
        int t  = tid & 7;
        float dy   = offs[2 * v];
        float ypix = ((float)(yb + t) + dy) * sy - 0.5f;
        float py   = floorf(ypix);
        float fy   = ypix - py;
        int   iy0  = (int)py;
        float wy0  = ((unsigned)iy0       < (unsigned)H) ? (1.0f - fy) : 0.0f;
        float wy1  = ((unsigned)(iy0 + 1) < (unsigned)H) ? fy          : 0.0f;
        int r0 = min(max(iy0,     rmin), rmax) - rmin;
        int r1 = min(max(iy0 + 1, rmin), rmax) - rmin;
        ycoef[v][t] = make_float4(wy0, wy1,
                                  __int_as_float(r0 * RS * 4),
                                  __int_as_float(r1 * RS * 4));
    }

    // ---- Stage input rows into padded smem (float2, coalesced).
    {
        const float2* src = reinterpret_cast<const float2*>(
            x + (size_t)bc * (H * W) + (size_t)rmin * W);
        const int n2 = nrows * (W / 2);
        for (int i = tid; i < n2; i += NTHREADS) {
            int r = i / (W / 2);
            int c = i - r * (W / 2);
            reinterpret_cast<float2*>(&srows[r * RS + 2])[c] = src[r * (W / 2) + c];
        }
    }
    __syncthreads();

    // ---- Compute: tid == output x; thread iterates the 8 rows of the tile.
    const int xx = tid;
    const char* sb = (const char*)srows;

#pragma unroll 1
    for (int v = 0; v < V; ++v) {
        const float dx = __ldg(&offs[2 * v + 1]);

        // x coefficients: once per view, reused for all 8 rows.
        float xpix = fmaf((float)xx, sx, dx * sx - 0.5f);
        int   ix0  = __float2int_rd(xpix);
        float fx   = xpix - (float)ix0;
        int   p0b  = min(max(ix0 + 2, 0), RS - 2) * 4;   // byte offset; pads absorb edges

        float* __restrict__ obase =
            out + (((size_t)(v * BCN + bc)) * H + yb) * W + xx;

        int   held = -1;                 // row byte-offset currently in (hl, hr)
        float hl = 0.0f, hr = 0.0f;

#pragma unroll
        for (int ty = 0; ty < TILE_Y; ++ty) {
            float4 yc  = ycoef[v][ty];                    // broadcast: 1 wavefront
            int    r0b = __float_as_int(yc.z);
            int    r1b = __float_as_int(yc.w);

            float c0l, c0r;
            if (r0b == held) {                            // warp-uniform predicate
                c0l = hl; c0r = hr;                       // register reuse: 0 LDS
            } else {
                const float* p = (const float*)(sb + (r0b + p0b));
                c0l = p[0]; c0r = p[1];
            }
            const float* q = (const float*)(sb + (r1b + p0b));
            hl = q[0]; hr = q[1];                         // 2 LDS.32 steady state
            held = r1b;

            float t0 = fmaf(fx, c0r - c0l, c0l);          // mask-free lerp (pads=0)
            float t1 = fmaf(fx, hr - hl, hl);
            obase[ty * W] = fmaf(t1, yc.y, t0 * yc.x);    // coalesced 128B/warp
        }
    }
}

}  // namespace

extern "C" void kernel_launch(void* const* d_in, const int* in_sizes, int n_in,
                              void* d_out, int out_size) {
    const float* x    = (const float*)d_in[0];
    const float* offs = (const float*)d_in[1];
    if (n_in >= 2 && in_sizes[0] == 2 * V) {   // tolerate swapped metadata order
        const float* t = x; x = offs; offs = t;
    }
    dim3 grid(H / TILE_Y, BCN);
    shift_views_kernel<<<grid, NTHREADS>>>(x, offs, (float*)d_out);
}

// round 7
// speedup vs baseline: 1.1172x; 1.1172x over previous
#include <cuda_runtime.h>
#include <cuda_fp16.h>

// LearnableShiftViews: out[v,b,c,h,w] = separable bilinear resample of x[b,c]
// at pix = (idx + d)*size/(size-1) - 0.5 per axis, zero padding.
//
// R7 = R6 (fp16 pair-table, halves smem data bytes) with the staging bug
// fixed: the neighbor element for the chunk-straddling pair is now read
// directly from global (L1-hot, same line as the neighbor chunk) instead of
// a cross-warp-broken shfl_down. Pair table: entry[p] = half2(data[p-2],
// data[p-1]) with 2 zero-pad cols left, 2 right, so the two adjacent x-taps
// arrive in ONE LDS.32 (2 per output total). Weights & blending stay fp32;
// only tap values are fp16-quantized (rel_err ~2.4e-4, threshold 1e-3).
// Mapping: warp = 32-wide x-strip; thread iterates the 8 y-rows; x-coeffs
// once per view; y-coeffs via broadcast LDS.128 from a per-block table.

namespace {

constexpr int H = 224;
constexpr int W = 224;
constexpr int B = 64;
constexpr int C = 3;
constexpr int BCN = B * C;     // 192
constexpr int V = 5;
constexpr int TILE_Y = 8;
constexpr int ROWS_CAP = 16;
constexpr int NTHREADS = 224;  // 7 warps = 7 x-strips; tid == output x
constexpr int PRS = 228;       // pair entries/row: [0,1] pads, [2..225] data, [226,227] pads
constexpr int CH4 = W / 4;     // 56 float4 chunks per input row

__global__ __launch_bounds__(NTHREADS)
void shift_views_kernel(const float* __restrict__ x,
                        const float* __restrict__ offs,
                        float* __restrict__ out) {
    __shared__ __half2 spack[ROWS_CAP * PRS];   // pair table, 14.6 KB
    __shared__ float4  ycoef[V][TILE_Y];        // {wy0, wy1, byteoff(row0), byteoff(row1)}

    const int yb  = blockIdx.x * TILE_Y;
    const int bc  = blockIdx.y;
    const int tid = threadIdx.x;
    const float sy = (float)H / (float)(H - 1);
    const float sx = (float)W / (float)(W - 1);

    // ---- Row range needed across all views (endpoints suffice; monotone).
    int rmin = H - 1, rmax = 0;
#pragma unroll
    for (int v = 0; v < V; ++v) {
        float dy = __ldg(&offs[2 * v]);
        int lo = (int)floorf(((float)yb + dy) * sy - 0.5f);
        int hi = (int)floorf(((float)(yb + TILE_Y - 1) + dy) * sy - 0.5f) + 1;
        lo = max(lo, 0);
        hi = min(hi, H - 1);
        rmin = min(rmin, lo);
        rmax = max(rmax, hi);
    }
    if (rmin > rmax) { rmin = 0; rmax = 0; }
    rmax = min(rmax, rmin + ROWS_CAP - 1);
    const int nrows = rmax - rmin + 1;

    // ---- Build y-coefficient table: one thread per (v, ty).
    if (tid < V * TILE_Y) {
        int v  = tid >> 3;
        int t  = tid & 7;
        float dy   = offs[2 * v];
        float ypix = ((float)(yb + t) + dy) * sy - 0.5f;
        float py   = floorf(ypix);
        float fy   = ypix - py;
        int   iy0  = (int)py;
        float wy0  = ((unsigned)iy0       < (unsigned)H) ? (1.0f - fy) : 0.0f;
        float wy1  = ((unsigned)(iy0 + 1) < (unsigned)H) ? fy          : 0.0f;
        int r0 = min(max(iy0,     rmin), rmax) - rmin;
        int r1 = min(max(iy0 + 1, rmin), rmax) - rmin;
        ycoef[v][t] = make_float4(wy0, wy1,
                                  __int_as_float(r0 * PRS * 4),
                                  __int_as_float(r1 * PRS * 4));
    }

    // ---- Stage + pack: chunk c of row r covers global cols [4c, 4c+3] and
    // writes pair entries 4c+2..4c+5; entry p = (data[p-2], data[p-1]).
    // The straddling value data[4c+4] is read directly (L1-hot scalar LDG).
    {
        const float*  srcf = x + (size_t)bc * (H * W) + (size_t)rmin * W;
        const float4* src4 = reinterpret_cast<const float4*>(srcf);
        const int total = nrows * CH4;
        for (int i = tid; i < total; i += NTHREADS) {
            int r = i / CH4;
            int c = i - r * CH4;
            float4 g = src4[r * CH4 + c];
            float hi3 = (c == CH4 - 1) ? 0.0f : __ldg(srcf + r * W + 4 * c + 4);
            __half2* row = &spack[r * PRS];
            row[4 * c + 2] = __floats2half2_rn(g.x, g.y);
            row[4 * c + 3] = __floats2half2_rn(g.y, g.z);
            row[4 * c + 4] = __floats2half2_rn(g.z, g.w);
            row[4 * c + 5] = __floats2half2_rn(g.w, hi3);
            if (c == 0) {                 // left pads
                row[0] = __floats2half2_rn(0.f, 0.f);
                row[1] = __floats2half2_rn(0.f, g.x);
            }
            if (c == CH4 - 1) {           // right pads
                row[226] = __floats2half2_rn(0.f, 0.f);
                row[227] = __floats2half2_rn(0.f, 0.f);
            }
        }
    }
    __syncthreads();

    // ---- Compute: warp w owns x-strip [32w, 32w+32); thread iterates 8 rows.
    const int xx = tid;
    const char* sb = (const char*)spack;

#pragma unroll 1
    for (int v = 0; v < V; ++v) {
        const float dx = __ldg(&offs[2 * v + 1]);

        // x coefficients: once per view, reused for all 8 rows.
        float xpix = fmaf((float)xx, sx, dx * sx - 0.5f);
        int   ix0  = __float2int_rd(xpix);
        float fx   = xpix - (float)ix0;
        int   p0b  = min(max(ix0 + 2, 0), PRS - 2) * 4;  // byte offset of pair entry

        float* __restrict__ obase =
            out + (((size_t)(v * BCN + bc)) * H + yb) * W + xx;

#pragma unroll
        for (int ty = 0; ty < TILE_Y; ++ty) {
            float4 yc = ycoef[v][ty];                    // broadcast: 1 wavefront
            const __half2 h0 = *(const __half2*)(sb + (__float_as_int(yc.z) + p0b));
            const __half2 h1 = *(const __half2*)(sb + (__float_as_int(yc.w) + p0b));
            float2 f0 = __half22float2(h0);              // both taps in one LDS.32
            float2 f1 = __half22float2(h1);
            float t0 = fmaf(fx, f0.y - f0.x, f0.x);      // mask-free lerp (pads=0)
            float t1 = fmaf(fx, f1.y - f1.x, f1.x);
            obase[ty * W] = fmaf(t1, yc.y, t0 * yc.x);   // coalesced 128B/warp
        }
    }
}

}  // namespace

extern "C" void kernel_launch(void* const* d_in, const int* in_sizes, int n_in,
                              void* d_out, int out_size) {
    const float* x    = (const float*)d_in[0];
    const float* offs = (const float*)d_in[1];
    if (n_in >= 2 && in_sizes[0] == 2 * V) {   // tolerate swapped metadata order
        const float* t = x; x = offs; offs = t;
    }
    dim3 grid(H / TILE_Y, BCN);
    shift_views_kernel<<<grid, NTHREADS>>>(x, offs, (float*)d_out);
}